// round 6
// baseline (speedup 1.0000x reference)
#include <cuda_runtime.h>
#include <cuda_bf16.h>
#include <cstdint>

// NeRF volume rendering compositing, GB300 (sm_103a).
// rgb: [B, 64, 3] f32, sigma: [B, 64] f32
// out: [B*3] rgb_map ++ [B] depth_map (f32)
//
// 4 rays per warp (two 2-ray pairs), 16 lanes per ray, 4 samples per lane.
// All 8 LDG.128 per thread are front-batched (MLP 8) and streaming (__ldcs).
// No smem, no block barriers. Width-16 segmented shuffle scan + reduction.

#define NERF_S 64

struct RayOut { float r, g, b, d; };

__device__ __forceinline__ RayOut composite(
    float4 sg, float4 c0, float4 c1, float4 c2, int j)
{
    float e0 = __expf(-sg.x);
    float e1 = __expf(-sg.y);
    float e2 = __expf(-sg.z);
    float e3 = __expf(-sg.w);

    float t0 = e0 + 1e-10f;
    float t1 = e1 + 1e-10f;
    float t2 = e2 + 1e-10f;
    float t3 = e3 + 1e-10f;

    // local exclusive products
    float l1 = t0;
    float l2 = t0 * t1;
    float l3 = l2 * t2;
    float p  = l3 * t3;

    // width-16 inclusive product scan (4 steps)
    float incl = p;
    #pragma unroll
    for (int off = 1; off < 16; off <<= 1) {
        float v = __shfl_up_sync(0xffffffffu, incl, off, 16);
        if (j >= off) incl *= v;
    }
    float E = __shfl_up_sync(0xffffffffu, incl, 1, 16);
    if (j == 0) E = 1.0f;

    float w0 = (1.0f - e0) * E;
    float w1 = (1.0f - e1) * (E * l1);
    float w2 = (1.0f - e2) * (E * l2);
    float w3 = (1.0f - e3) * (E * l3);

    RayOut o;
    o.r = w0 * c0.x + w1 * c0.w + w2 * c1.z + w3 * c2.y;
    o.g = w0 * c0.y + w1 * c1.x + w2 * c1.w + w3 * c2.z;
    o.b = w0 * c0.z + w1 * c1.y + w2 * c2.x + w3 * c2.w;

    const float step = 4.0f / 63.0f;       // linspace(2, 6, 64)
    const float tv = 2.0f + step * (float)(4 * j);
    o.d = w0 * tv
        + w1 * (tv + step)
        + w2 * (tv + 2.0f * step)
        + w3 * (tv + 3.0f * step);

    // width-16 butterfly reduction
    #pragma unroll
    for (int off = 8; off > 0; off >>= 1) {
        o.r += __shfl_xor_sync(0xffffffffu, o.r, off, 16);
        o.g += __shfl_xor_sync(0xffffffffu, o.g, off, 16);
        o.b += __shfl_xor_sync(0xffffffffu, o.b, off, 16);
        o.d += __shfl_xor_sync(0xffffffffu, o.d, off, 16);
    }
    return o;
}

__global__ __launch_bounds__(256) void nerf_render_kernel(
    const float4* __restrict__ rgb4,   // [B*48] float4
    const float4* __restrict__ sig4,   // [B*16] float4
    float* __restrict__ out,
    int n_rays)
{
    const int warp_g = (blockIdx.x * blockDim.x + threadIdx.x) >> 5;
    const int lane   = threadIdx.x & 31;
    const int half   = lane >> 4;          // ray within pair
    const int j      = lane & 15;          // segment position (0..15)

    const int rayA = warp_g * 4 + half;    // pair 0
    const int rayB = rayA + 2;             // pair 1
    if (rayA >= n_rays) return;
    const bool hasB = (rayB < n_rays);

    // ---- front-batched streaming loads: 8 x LDG.128, all coalesced ----
    const float4 sgA = __ldcs(sig4 + (size_t)warp_g * 64 + lane);
    float4 sgB = make_float4(0.f, 0.f, 0.f, 0.f);
    if (hasB) sgB = __ldcs(sig4 + (size_t)warp_g * 64 + 32 + lane);

    const float4* rpA = rgb4 + (size_t)rayA * 48 + 3 * j;
    float4 a0 = __ldcs(rpA + 0);
    float4 a1 = __ldcs(rpA + 1);
    float4 a2 = __ldcs(rpA + 2);

    float4 b0 = a0, b1 = a1, b2 = a2;
    if (hasB) {
        const float4* rpB = rgb4 + (size_t)rayB * 48 + 3 * j;
        b0 = __ldcs(rpB + 0);
        b1 = __ldcs(rpB + 1);
        b2 = __ldcs(rpB + 2);
    }

    // ---- pair 0 ----
    RayOut oA = composite(sgA, a0, a1, a2, j);
    if (j == 0) {
        out[(size_t)rayA * 3 + 0] = oA.r;
        out[(size_t)rayA * 3 + 1] = oA.g;
        out[(size_t)rayA * 3 + 2] = oA.b;
        out[(size_t)n_rays * 3 + rayA] = oA.d;
    }

    // ---- pair 1 ----
    if (hasB) {
        RayOut oB = composite(sgB, b0, b1, b2, j);
        if (j == 0) {
            out[(size_t)rayB * 3 + 0] = oB.r;
            out[(size_t)rayB * 3 + 1] = oB.g;
            out[(size_t)rayB * 3 + 2] = oB.b;
            out[(size_t)n_rays * 3 + rayB] = oB.d;
        }
    }
}

extern "C" void kernel_launch(void* const* d_in, const int* in_sizes, int n_in,
                              void* d_out, int out_size)
{
    const float4* rgb4 = (const float4*)d_in[0];   // [B, 64, 3]
    const float4* sig4 = (const float4*)d_in[1];   // [B, 64]
    float* out = (float*)d_out;

    const int n_rays = in_sizes[1] / NERF_S;

    // 256 threads = 8 warps = 32 rays per block
    const int rays_per_block = 32;
    const int blocks = (n_rays + rays_per_block - 1) / rays_per_block;
    nerf_render_kernel<<<blocks, 256>>>(rgb4, sig4, out, n_rays);
}